// round 11
// baseline (speedup 1.0000x reference)
#include <cuda_runtime.h>
#include <cuda_fp16.h>
#include <cstdint>

#define BATCH 4
#define SEQ   4096
#define HID   1024
#define NST   16
#define NROWS (BATCH*SEQ)       // 16384
#define CHUNK 64
#define NCH   (SEQ/CHUNK)       // 64
#define NCHT  (BATCH*NCH)       // 256
#define LN_EPS 1e-5f

// ---- scratch (static device globals) ----
__device__ float g_xB[NROWS*NST];
__device__ float g_states[NROWS*NST];
__device__ float g_finals[NCHT*NST];
__device__ float g_carry[NCHT*NST];
__device__ float g_Apow[(CHUNK+1)*NST*NST];       // A^0..A^64
__device__ float g_Qpow[NCH*NST*NST];             // (A^64)^0..^63
__device__ __half g_xh[(size_t)NROWS*HID];
__device__ __half g_Dh[(size_t)HID*HID];

// ================= PTX helpers ====
__device__ __forceinline__ uint32_t smem_u32(const void* p) {
    uint32_t a;
    asm("{ .reg .u64 t; cvta.to.shared.u64 t, %1; cvt.u32.u64 %0, t; }" : "=r"(a) : "l"(p));
    return a;
}
__device__ __forceinline__ void cp16(uint32_t dst, const void* src) {
    asm volatile("cp.async.cg.shared.global [%0], [%1], 16;" :: "r"(dst), "l"(src) : "memory");
}
__device__ __forceinline__ void cp_commit() {
    asm volatile("cp.async.commit_group;" ::: "memory");
}
__device__ __forceinline__ void cp_wait1() {
    asm volatile("cp.async.wait_group 1;" ::: "memory");
}
__device__ __forceinline__ void cp_wait0() {
    asm volatile("cp.async.wait_group 0;" ::: "memory");
}
__device__ __forceinline__ void ldsm4(uint32_t* r, uint32_t a) {
    asm volatile("ldmatrix.sync.aligned.m8n8.x4.shared.b16 {%0,%1,%2,%3}, [%4];"
                 : "=r"(r[0]), "=r"(r[1]), "=r"(r[2]), "=r"(r[3]) : "r"(a));
}
__device__ __forceinline__ void mma16816h(float* c, const uint32_t* a, uint32_t b0, uint32_t b1) {
    asm volatile(
        "mma.sync.aligned.m16n8k16.row.col.f32.f16.f16.f32 "
        "{%0,%1,%2,%3}, {%4,%5,%6,%7}, {%8,%9}, {%0,%1,%2,%3};"
        : "+f"(c[0]), "+f"(c[1]), "+f"(c[2]), "+f"(c[3])
        : "r"(a[0]), "r"(a[1]), "r"(a[2]), "r"(a[3]), "r"(b0), "r"(b1));
}
static __device__ __forceinline__ uint32_t swz(uint32_t x) { return x ^ ((x >> 3) & 0x70); }

// ============================================================
// K0: D -> fp16
// ============================================================
__global__ __launch_bounds__(256) void k_cvtD(const float* __restrict__ D,
                                              __half* __restrict__ Dh, int n4) {
    int i = blockIdx.x * 256 + threadIdx.x;
    if (i >= n4) return;
    float4 v = ((const float4*)D)[i];
    __half2 p0 = __halves2half2(__float2half_rn(v.x), __float2half_rn(v.y));
    __half2 p1 = __halves2half2(__float2half_rn(v.z), __float2half_rn(v.w));
    ((uint2*)Dh)[i] = make_uint2(*(uint32_t*)&p0, *(uint32_t*)&p1);
}

// ============================================================
// K1: xB = x @ B^T, fused with x -> fp16 store
// ============================================================
__global__ __launch_bounds__(256) void k_xBc(const float* __restrict__ x,
                                             const float* __restrict__ B,
                                             __half* __restrict__ xh) {
    __shared__ float xs[128][33];
    __shared__ float Bs[NST][33];
    const int tid = threadIdx.x;
    const int rowbase = blockIdx.x * 128;
    const int n  = tid & 15;
    const int rg = tid >> 4;

    float acc[8];
#pragma unroll
    for (int i = 0; i < 8; i++) acc[i] = 0.f;

    for (int kb = 0; kb < HID; kb += 32) {
#pragma unroll
        for (int p = 0; p < 4; p++) {
            int idx = tid + p * 256;
            int r  = idx >> 3;
            int kq = (idx & 7) * 4;
            size_t gofs = (size_t)(rowbase + r) * HID + kb + kq;
            float4 v = *(const float4*)&x[gofs];
            xs[r][kq+0] = v.x; xs[r][kq+1] = v.y; xs[r][kq+2] = v.z; xs[r][kq+3] = v.w;
            __half2 p0 = __halves2half2(__float2half_rn(v.x), __float2half_rn(v.y));
            __half2 p1 = __halves2half2(__float2half_rn(v.z), __float2half_rn(v.w));
            *(uint2*)&xh[gofs] = make_uint2(*(uint32_t*)&p0, *(uint32_t*)&p1);
        }
        if (tid < 128) {
            int bn = tid >> 3;
            int kq = (tid & 7) * 4;
            float4 v = *(const float4*)&B[bn * HID + kb + kq];
            Bs[bn][kq+0] = v.x; Bs[bn][kq+1] = v.y; Bs[bn][kq+2] = v.z; Bs[bn][kq+3] = v.w;
        }
        __syncthreads();
#pragma unroll
        for (int k = 0; k < 32; k++) {
            float bv = Bs[n][k];
#pragma unroll
            for (int r = 0; r < 8; r++) acc[r] += xs[rg*8 + r][k] * bv;
        }
        __syncthreads();
    }
#pragma unroll
    for (int r = 0; r < 8; r++)
        g_xB[(rowbase + rg*8 + r) * NST + n] = acc[r];
}

// ============================================================
// K2: combined scan + powers (blocks 0..15 scan; block 16 powers)
// ============================================================
__global__ __launch_bounds__(256) void k_scanpow(const float* __restrict__ A) {
    __shared__ float sP[33][256];
    const int tid = threadIdx.x;

    if (blockIdx.x < NCHT / 16) {
        const int lane16 = tid & 15;
        const int cid = blockIdx.x * 16 + (tid >> 4);   // 0..255
        const int b = cid >> 6;
        const int c = cid & (NCH - 1);
        const int gb = tid & 16;

        float Arow[NST];
#pragma unroll
        for (int k = 0; k < NST; k++) Arow[k] = A[lane16 * NST + k];

        float s = 0.f;
        const int base = (b * SEQ + c * CHUNK) * NST;
        for (int i = 0; i < CHUNK; i++) {
            float u  = g_xB[base + i * NST + lane16];
            float ns = u;
#pragma unroll
            for (int k = 0; k < NST; k++)
                ns += Arow[k] * __shfl_sync(0xffffffffu, s, gb | k, 32);
            s = ns;
            g_states[base + i * NST + lane16] = s;
        }
        g_finals[cid * NST + lane16] = s;
        return;
    }

    // ---- powers branch (single block) ----
    const int t = tid;
    const int n = t >> 4, m = t & 15;
    const float id = (n == m) ? 1.f : 0.f;
    g_Apow[t] = id;
    g_Apow[256 + t] = A[t];
    sP[1][t] = A[t];
    __syncthreads();
#pragma unroll
    for (int lvl = 1; lvl <= 32; lvl <<= 1) {
        float rowL[16];
#pragma unroll
        for (int k = 0; k < 16; k++) rowL[k] = sP[lvl][n * 16 + k];
        const int qmax = (lvl <= 64 - lvl) ? lvl : 64 - lvl;
        for (int q = 1; q <= qmax; q++) {
            float v = 0.f;
#pragma unroll
            for (int k = 0; k < 16; k++) v += rowL[k] * sP[q][k * 16 + m];
            g_Apow[(lvl + q) * 256 + t] = v;
            if (lvl + q <= 32) sP[lvl + q][t] = v;
        }
        __syncthreads();
    }
    float a64 = g_Apow[64 * 256 + t];
    g_Qpow[t] = id;
    g_Qpow[256 + t] = a64;
    __syncthreads();
    sP[1][t] = a64;
    __syncthreads();
#pragma unroll
    for (int lvl = 1; lvl <= 32; lvl <<= 1) {
        float rowL[16];
#pragma unroll
        for (int k = 0; k < 16; k++) rowL[k] = sP[lvl][n * 16 + k];
        const int qmax = (lvl <= 63 - lvl) ? lvl : 63 - lvl;
        for (int q = 1; q <= qmax; q++) {
            float v = 0.f;
#pragma unroll
            for (int k = 0; k < 16; k++) v += rowL[k] * sP[q][k * 16 + m];
            g_Qpow[(lvl + q) * 256 + t] = v;
            if (lvl + q <= 32) sP[lvl + q][t] = v;
        }
        __syncthreads();
    }
}

// ============================================================
// K3: carry[b,c] = sum_{j<c} Q_{c-1-j} @ finals[b,j]
// ============================================================
__global__ __launch_bounds__(256) void k_carry2() {
    __shared__ float part[16][17];
    const int gid = blockIdx.x;            // 0..255
    const int b = gid >> 6;
    const int c = gid & (NCH - 1);
    const int n  = threadIdx.x & 15;
    const int jg = threadIdx.x >> 4;       // 0..15

    float acc = 0.f;
    for (int j = jg; j < c; j += 16) {
        const float* Qr = &g_Qpow[(c - 1 - j) * 256 + n * NST];
        const float* f  = &g_finals[(b * NCH + j) * NST];
#pragma unroll
        for (int k = 0; k < NST; k++) acc += Qr[k] * f[k];
    }
    part[jg][n] = acc;
    __syncthreads();
    if (threadIdx.x < 16) {
        float s = 0.f;
#pragma unroll
        for (int k = 0; k < 16; k++) s += part[k][threadIdx.x];
        g_carry[gid * NST + threadIdx.x] = s;
    }
}

// ============================================================
// K4: mma.sync fp16 GEMM: out = states_fixed @ C^T + x @ D^T
// fixup (states += A^{i+1} @ carry) applied in the prologue.
// 128x128 tile, 8 warps (32x64 warp tile), BK=64, 2-stage cp.async
// ============================================================
#define BKC 64
#define NKC (HID/BKC)          // 16
#define OFF_AH 0
#define OFF_BH 16384
#define STAGE  32768
#define OFF_SS (2*STAGE)                 // states tile 128x17 f32
#define OFF_CS (OFF_SS + 128*17*4)       // C tile 128x17 f32
#define DYN_SMEM (OFF_CS + 128*17*4)     // 82944

__global__ __launch_bounds__(256, 1)
void k_mma(const float* __restrict__ C, float* __restrict__ out) {
    extern __shared__ __align__(1024) char dsm[];
    const int tid  = threadIdx.x;
    const int lane = tid & 31;
    const int wid  = tid >> 5;
    const int wm   = wid & 3;
    const int wn   = wid >> 2;
    const int g    = lane >> 2;
    const int tig  = lane & 3;
    const int rowbase = blockIdx.y * 128;
    const int colbase = blockIdx.x * 128;
    const uint32_t sbase = smem_u32(dsm);
    float* Ss = (float*)(dsm + OFF_SS);
    float* Cs = (float*)(dsm + OFF_CS);

    // ---- issue chunk 0 loads ----
#pragma unroll
    for (int p = 0; p < 4; p++) {
        int idx = p * 256 + tid;
        int r = idx >> 3, c8 = (idx & 7) * 8;
        uint32_t so = swz((uint32_t)(r * 128 + c8 * 2));
        size_t gA = (size_t)(rowbase + r) * HID + c8;
        size_t gB = (size_t)(colbase + r) * HID + c8;
        cp16(sbase + OFF_AH + so, g_xh + gA);
        cp16(sbase + OFF_BH + so, g_Dh + gB);
    }
    cp_commit();

    // ---- load states/C tiles; apply scan fix-up to states in regs ----
#pragma unroll
    for (int q = 0; q < 2; q++) {
        int idx4 = tid + q * 256;
        int r = idx4 >> 2, kq = (idx4 & 3) * 4;
        const int row = rowbase + r;
        const int b  = row >> 12;
        const int tt = row & (SEQ - 1);
        const int cc = tt >> 6;
        const int ii = tt & (CHUNK - 1);
        const float* carr = &g_carry[(b * NCH + cc) * NST];
        const float* Pr   = &g_Apow[(ii + 1) * 256];
        float4 s = *(const float4*)&g_states[(size_t)row * NST + kq];
        float f0 = 0.f, f1 = 0.f, f2 = 0.f, f3 = 0.f;
#pragma unroll
        for (int k = 0; k < NST; k++) {
            float cv = carr[k];
            f0 += Pr[(kq + 0) * NST + k] * cv;
            f1 += Pr[(kq + 1) * NST + k] * cv;
            f2 += Pr[(kq + 2) * NST + k] * cv;
            f3 += Pr[(kq + 3) * NST + k] * cv;
        }
        s.x += f0; s.y += f1; s.z += f2; s.w += f3;
        Ss[r * 17 + kq + 0] = s.x; Ss[r * 17 + kq + 1] = s.y;
        Ss[r * 17 + kq + 2] = s.z; Ss[r * 17 + kq + 3] = s.w;

        float4 c = *(const float4*)&C[(size_t)(colbase + r) * NST + kq];
        Cs[r * 17 + kq + 0] = c.x; Cs[r * 17 + kq + 1] = c.y;
        Cs[r * 17 + kq + 2] = c.z; Cs[r * 17 + kq + 3] = c.w;
    }
    __syncthreads();

    // ---- init acc = states @ C^T (K=16, fp32 exact) ----
    float acc[2][8][4];
#pragma unroll
    for (int i = 0; i < 2; i++) {
        const int m0 = wm * 32 + i * 16 + g;
        float s0[16], s1[16];
#pragma unroll
        for (int k = 0; k < 16; k++) { s0[k] = Ss[m0 * 17 + k]; s1[k] = Ss[(m0 + 8) * 17 + k]; }
#pragma unroll
        for (int j = 0; j < 8; j++) {
            const int n0 = wn * 64 + j * 8 + tig * 2;
            float c0 = 0.f, c1 = 0.f, c2 = 0.f, c3 = 0.f;
#pragma unroll
            for (int k = 0; k < 16; k++) {
                float e0 = Cs[n0 * 17 + k], e1 = Cs[(n0 + 1) * 17 + k];
                c0 += s0[k] * e0; c1 += s0[k] * e1;
                c2 += s1[k] * e0; c3 += s1[k] * e1;
            }
            acc[i][j][0] = c0; acc[i][j][1] = c1; acc[i][j][2] = c2; acc[i][j][3] = c3;
        }
    }

    // ---- main K loop, 2-stage ----
    for (int c = 0; c < NKC; c++) {
        if (c + 1 < NKC) {
            const uint32_t sb = sbase + ((c + 1) & 1) * STAGE;
            const int kb = (c + 1) * BKC;
#pragma unroll
            for (int p = 0; p < 4; p++) {
                int idx = p * 256 + tid;
                int r = idx >> 3, c8 = (idx & 7) * 8;
                uint32_t so = swz((uint32_t)(r * 128 + c8 * 2));
                size_t gA = (size_t)(rowbase + r) * HID + kb + c8;
                size_t gB = (size_t)(colbase + r) * HID + kb + c8;
                cp16(sb + OFF_AH + so, g_xh + gA);
                cp16(sb + OFF_BH + so, g_Dh + gB);
            }
            cp_commit();
            cp_wait1();
        } else {
            cp_wait0();
        }
        __syncthreads();

        const uint32_t sb = sbase + (c & 1) * STAGE;
#pragma unroll
        for (int ks = 0; ks < BKC / 16; ks++) {
            uint32_t aH[2][4];
#pragma unroll
            for (int i = 0; i < 2; i++) {
                uint32_t off = swz((uint32_t)((wm * 32 + i * 16 + (lane & 15)) * 128 +
                                              (ks * 16 + (lane >> 4) * 8) * 2));
                ldsm4(aH[i], sb + OFF_AH + off);
            }
#pragma unroll
            for (int p = 0; p < 4; p++) {
                uint32_t nloc = wn * 64 + p * 16 + ((lane >> 4) & 1) * 8 + (lane & 7);
                uint32_t kc = ks * 16 + ((lane >> 3) & 1) * 8;
                uint32_t off = swz(nloc * 128 + kc * 2);
                uint32_t rh[4];
                ldsm4(rh, sb + OFF_BH + off);
                mma16816h(acc[0][2*p],   aH[0], rh[0], rh[1]);
                mma16816h(acc[0][2*p+1], aH[0], rh[2], rh[3]);
                mma16816h(acc[1][2*p],   aH[1], rh[0], rh[1]);
                mma16816h(acc[1][2*p+1], aH[1], rh[2], rh[3]);
            }
        }
        __syncthreads();
    }

    // ---- epilogue: pure stores ----
#pragma unroll
    for (int i = 0; i < 2; i++) {
        const int m0 = rowbase + wm * 32 + i * 16 + g;
#pragma unroll
        for (int j = 0; j < 8; j++) {
            const int n0 = colbase + wn * 64 + j * 8 + tig * 2;
            *(float2*)&out[(size_t)m0 * HID + n0]       = make_float2(acc[i][j][0], acc[i][j][1]);
            *(float2*)&out[(size_t)(m0 + 8) * HID + n0] = make_float2(acc[i][j][2], acc[i][j][3]);
        }
    }
}

// ============================================================
// K5: LayerNorm in place
// ============================================================
__global__ __launch_bounds__(256) void k_ln(float* __restrict__ out,
                                            const float* __restrict__ gamma,
                                            const float* __restrict__ beta) {
    __shared__ float rs[8], rs2[8];
    const int row = blockIdx.x;
    const int tid = threadIdx.x;

    float4 v = *(const float4*)&out[(size_t)row * HID + tid * 4];
    float s  = v.x + v.y + v.z + v.w;
    float s2 = v.x*v.x + v.y*v.y + v.z*v.z + v.w*v.w;
#pragma unroll
    for (int o = 16; o > 0; o >>= 1) {
        s  += __shfl_down_sync(0xffffffffu, s,  o);
        s2 += __shfl_down_sync(0xffffffffu, s2, o);
    }
    if ((tid & 31) == 0) { rs[tid >> 5] = s; rs2[tid >> 5] = s2; }
    __syncthreads();
    float ts = 0.f, ts2 = 0.f;
#pragma unroll
    for (int i = 0; i < 8; i++) { ts += rs[i]; ts2 += rs2[i]; }

    const float mu  = ts * (1.f / HID);
    const float var = ts2 * (1.f / HID) - mu * mu;
    const float inv = rsqrtf(var + LN_EPS);

    float4 gm = *(const float4*)&gamma[tid * 4];
    float4 bt = *(const float4*)&beta[tid * 4];
    v.x = (v.x - mu) * inv * gm.x + bt.x;
    v.y = (v.y - mu) * inv * gm.y + bt.y;
    v.z = (v.z - mu) * inv * gm.z + bt.z;
    v.w = (v.w - mu) * inv * gm.w + bt.w;
    *(float4*)&out[(size_t)row * HID + tid * 4] = v;
}

// ============================================================
extern "C" void kernel_launch(void* const* d_in, const int* in_sizes, int n_in,
                              void* d_out, int out_size) {
    const float* x     = (const float*)d_in[0];
    const float* A     = (const float*)d_in[1];
    const float* B     = (const float*)d_in[2];
    const float* C     = (const float*)d_in[3];
    const float* D     = (const float*)d_in[4];
    const float* gamma = (const float*)d_in[5];
    const float* beta  = (const float*)d_in[6];
    float* out = (float*)d_out;
    (void)in_sizes; (void)n_in; (void)out_size;

    cudaFuncSetAttribute(k_mma, cudaFuncAttributeMaxDynamicSharedMemorySize, DYN_SMEM);

    __half *xh_p, *dh_p;
    cudaGetSymbolAddress((void**)&xh_p, g_xh);
    cudaGetSymbolAddress((void**)&dh_p, g_Dh);

    const int n4d = HID * HID / 4;

    // launch 0
    k_cvtD    <<<(n4d + 255) / 256, 256>>>(D, dh_p, n4d);
    // launch 1
    k_xBc     <<<NROWS / 128, 256>>>(x, B, xh_p);
    // launch 2
    k_scanpow <<<NCHT / 16 + 1, 256>>>(A);
    // launch 3
    k_carry2  <<<NCHT, 256>>>();
    // launch 4
    dim3 g3(HID / 128, NROWS / 128);
    k_mma     <<<g3, 256, DYN_SMEM>>>(C, out);
    // launch 5
    k_ln      <<<NROWS, 256>>>(out, gamma, beta);
}

// round 12
// speedup vs baseline: 1.0733x; 1.0733x over previous
#include <cuda_runtime.h>
#include <cuda_fp16.h>
#include <cstdint>

#define BATCH 4
#define SEQ   4096
#define HID   1024
#define NST   16
#define NROWS (BATCH*SEQ)       // 16384
#define CHUNK 32
#define NCH   (SEQ/CHUNK)       // 128
#define NCHT  (BATCH*NCH)       // 512
#define LN_EPS 1e-5f

// ---- scratch (static device globals) ----
__device__ float g_xB[NROWS*NST];
__device__ float g_states[NROWS*NST];
__device__ float g_finals[NCHT*NST];
__device__ float g_carry[NCHT*NST];
__device__ float g_Apow[(CHUNK+1)*NST*NST];       // A^0..A^32
__device__ float g_Qpow[NCH*NST*NST];             // (A^32)^0..^127
__device__ __half g_xh[(size_t)NROWS*HID];
__device__ __half g_Dh[(size_t)HID*HID];

// ================= PTX helpers ====
__device__ __forceinline__ uint32_t smem_u32(const void* p) {
    uint32_t a;
    asm("{ .reg .u64 t; cvta.to.shared.u64 t, %1; cvt.u32.u64 %0, t; }" : "=r"(a) : "l"(p));
    return a;
}
__device__ __forceinline__ void cp16(uint32_t dst, const void* src) {
    asm volatile("cp.async.cg.shared.global [%0], [%1], 16;" :: "r"(dst), "l"(src) : "memory");
}
__device__ __forceinline__ void cp_commit() {
    asm volatile("cp.async.commit_group;" ::: "memory");
}
__device__ __forceinline__ void cp_wait1() {
    asm volatile("cp.async.wait_group 1;" ::: "memory");
}
__device__ __forceinline__ void cp_wait0() {
    asm volatile("cp.async.wait_group 0;" ::: "memory");
}
__device__ __forceinline__ void ldsm4(uint32_t* r, uint32_t a) {
    asm volatile("ldmatrix.sync.aligned.m8n8.x4.shared.b16 {%0,%1,%2,%3}, [%4];"
                 : "=r"(r[0]), "=r"(r[1]), "=r"(r[2]), "=r"(r[3]) : "r"(a));
}
__device__ __forceinline__ void mma16816h(float* c, const uint32_t* a, uint32_t b0, uint32_t b1) {
    asm volatile(
        "mma.sync.aligned.m16n8k16.row.col.f32.f16.f16.f32 "
        "{%0,%1,%2,%3}, {%4,%5,%6,%7}, {%8,%9}, {%0,%1,%2,%3};"
        : "+f"(c[0]), "+f"(c[1]), "+f"(c[2]), "+f"(c[3])
        : "r"(a[0]), "r"(a[1]), "r"(a[2]), "r"(a[3]), "r"(b0), "r"(b1));
}
static __device__ __forceinline__ uint32_t swz(uint32_t x) { return x ^ ((x >> 3) & 0x70); }

// ============================================================
// K0: conversions: x -> fp16, D -> fp16 (standalone; fusion into
// k_xB measured +30us twice -- banned)
// ============================================================
__global__ __launch_bounds__(256) void k_cvt_all(const float* __restrict__ x,
                                                 const float* __restrict__ D,
                                                 __half* __restrict__ xh,
                                                 __half* __restrict__ Dh,
                                                 int n4x, int n4d) {
    int i = blockIdx.x * 256 + threadIdx.x;
    if (i < n4x) {
        float4 v = ((const float4*)x)[i];
        __half2 p0 = __halves2half2(__float2half_rn(v.x), __float2half_rn(v.y));
        __half2 p1 = __halves2half2(__float2half_rn(v.z), __float2half_rn(v.w));
        ((uint2*)xh)[i] = make_uint2(*(uint32_t*)&p0, *(uint32_t*)&p1);
    } else if (i < n4x + n4d) {
        int j = i - n4x;
        float4 v = ((const float4*)D)[j];
        __half2 p0 = __halves2half2(__float2half_rn(v.x), __float2half_rn(v.y));
        __half2 p1 = __halves2half2(__float2half_rn(v.z), __float2half_rn(v.w));
        ((uint2*)Dh)[j] = make_uint2(*(uint32_t*)&p0, *(uint32_t*)&p1);
    }
}

// ============================================================
// K1: xB[row,n] = sum_h x[row,h] * B[n,h]
// ============================================================
__global__ __launch_bounds__(256) void k_xB(const float* __restrict__ x,
                                            const float* __restrict__ B) {
    __shared__ float xs[128][33];
    __shared__ float Bs[NST][33];
    const int tid = threadIdx.x;
    const int rowbase = blockIdx.x * 128;
    const int n  = tid & 15;
    const int rg = tid >> 4;

    float acc[8];
#pragma unroll
    for (int i = 0; i < 8; i++) acc[i] = 0.f;

    for (int kb = 0; kb < HID; kb += 32) {
#pragma unroll
        for (int p = 0; p < 4; p++) {
            int idx = tid + p * 256;
            int r  = idx >> 3;
            int kq = (idx & 7) * 4;
            float4 v = *(const float4*)&x[(rowbase + r) * HID + kb + kq];
            xs[r][kq+0] = v.x; xs[r][kq+1] = v.y; xs[r][kq+2] = v.z; xs[r][kq+3] = v.w;
        }
        if (tid < 128) {
            int bn = tid >> 3;
            int kq = (tid & 7) * 4;
            float4 v = *(const float4*)&B[bn * HID + kb + kq];
            Bs[bn][kq+0] = v.x; Bs[bn][kq+1] = v.y; Bs[bn][kq+2] = v.z; Bs[bn][kq+3] = v.w;
        }
        __syncthreads();
#pragma unroll
        for (int k = 0; k < 32; k++) {
            float bv = Bs[n][k];
#pragma unroll
            for (int r = 0; r < 8; r++) acc[r] += xs[rg*8 + r][k] * bv;
        }
        __syncthreads();
    }
#pragma unroll
    for (int r = 0; r < 8; r++)
        g_xB[(rowbase + rg*8 + r) * NST + n] = acc[r];
}

// ============================================================
// K2: combined scan (blocks 0..31, CHUNK=32) + powers (block 32)
// dyn smem: 65 levels * 256 floats = 66560 B
// ============================================================
__global__ __launch_bounds__(256) void k_scanpow(const float* __restrict__ A) {
    extern __shared__ float sP[];   // 65 * 256 floats (powers block only)
    const int tid = threadIdx.x;

    if (blockIdx.x < NCHT / 16) {
        // ---- scan branch: 16 chunks per block, 16 lanes each ----
        const int lane16 = tid & 15;
        const int cid = blockIdx.x * 16 + (tid >> 4);   // 0..511
        const int b = cid >> 7;
        const int c = cid & (NCH - 1);
        const int gb = tid & 16;

        float Arow[NST];
#pragma unroll
        for (int k = 0; k < NST; k++) Arow[k] = A[lane16 * NST + k];

        float s = 0.f;
        const int base = (b * SEQ + c * CHUNK) * NST;
        for (int i = 0; i < CHUNK; i++) {
            float u  = g_xB[base + i * NST + lane16];
            float ns = u;
#pragma unroll
            for (int k = 0; k < NST; k++)
                ns += Arow[k] * __shfl_sync(0xffffffffu, s, gb | k, 32);
            s = ns;
            g_states[base + i * NST + lane16] = s;
        }
        g_finals[cid * NST + lane16] = s;
        return;
    }

    // ---- powers branch (single block): A^0..A^32, Q^0..Q^127 ----
    const int t = tid;
    const int n = t >> 4, m = t & 15;
    const float id = (n == m) ? 1.f : 0.f;

    g_Apow[t] = id;
    g_Apow[256 + t] = A[t];
    sP[256 + t] = A[t];
    __syncthreads();
#pragma unroll
    for (int lvl = 1; lvl <= 16; lvl <<= 1) {
        float rowL[16];
#pragma unroll
        for (int k = 0; k < 16; k++) rowL[k] = sP[lvl * 256 + n * 16 + k];
        for (int q = 1; q <= lvl; q++) {
            float v = 0.f;
#pragma unroll
            for (int k = 0; k < 16; k++) v += rowL[k] * sP[q * 256 + k * 16 + m];
            g_Apow[(lvl + q) * 256 + t] = v;
            sP[(lvl + q) * 256 + t] = v;
        }
        __syncthreads();
    }

    float base = sP[32 * 256 + t];      // A^32
    g_Qpow[t] = id;
    g_Qpow[256 + t] = base;
    __syncthreads();
    sP[256 + t] = base;
    __syncthreads();
#pragma unroll
    for (int lvl = 1; lvl <= 64; lvl <<= 1) {
        float rowL[16];
#pragma unroll
        for (int k = 0; k < 16; k++) rowL[k] = sP[lvl * 256 + n * 16 + k];
        const int qmax = (lvl <= 127 - lvl) ? lvl : 127 - lvl;
        for (int q = 1; q <= qmax; q++) {
            float v = 0.f;
#pragma unroll
            for (int k = 0; k < 16; k++) v += rowL[k] * sP[q * 256 + k * 16 + m];
            g_Qpow[(lvl + q) * 256 + t] = v;
            if (lvl + q <= 64) sP[(lvl + q) * 256 + t] = v;
        }
        __syncthreads();
    }
}
#define POW_SMEM (65 * 256 * 4)

// ============================================================
// K3: carry[b,c] = sum_{j<c} Q_{c-1-j} @ finals[b,j]
// one block per (b,c); j strided across 16 groups (<=8 iters)
// ============================================================
__global__ __launch_bounds__(256) void k_carry2() {
    __shared__ float part[16][17];
    const int gid = blockIdx.x;            // 0..511
    const int b = gid >> 7;
    const int c = gid & (NCH - 1);
    const int n  = threadIdx.x & 15;
    const int jg = threadIdx.x >> 4;       // 0..15

    float acc = 0.f;
    for (int j = jg; j < c; j += 16) {
        const float* Qr = &g_Qpow[(c - 1 - j) * 256 + n * NST];
        const float* f  = &g_finals[(b * NCH + j) * NST];
#pragma unroll
        for (int k = 0; k < NST; k++) acc += Qr[k] * f[k];
    }
    part[jg][n] = acc;
    __syncthreads();
    if (threadIdx.x < 16) {
        float s = 0.f;
#pragma unroll
        for (int k = 0; k < 16; k++) s += part[k][threadIdx.x];
        g_carry[gid * NST + threadIdx.x] = s;
    }
}

// ============================================================
// K4: fix-up: states += A^{i+1} @ carry
// ============================================================
__global__ __launch_bounds__(128) void k_fixup() {
    const int tid = threadIdx.x;
    const int n  = tid & 15;
    const int gb = tid & 16;
    const int row = blockIdx.x * 8 + (tid >> 4);
    const int b  = row >> 12;
    const int tt = row & (SEQ - 1);
    const int c  = tt >> 5;               // / CHUNK
    const int i  = tt & (CHUNK - 1);

    float cv = g_carry[(b * NCH + c) * NST + n];
    const float* Pr = &g_Apow[(i + 1) * 256 + n * NST];
    float v = 0.f;
#pragma unroll
    for (int k = 0; k < NST; k++)
        v += Pr[k] * __shfl_sync(0xffffffffu, cv, gb | k, 32);
    g_states[row * NST + n] += v;
}

// ============================================================
// K5: mma.sync fp16 single-pass GEMM (R10 champion, untouched):
// out = states @ C^T + x @ D^T
// 128x128 tile, 8 warps (32x64 warp tile), BK=64, 2-stage cp.async
// ============================================================
#define BKC 64
#define NKC (HID/BKC)          // 16
#define OFF_AH 0
#define OFF_BH 16384
#define STAGE  32768
#define OFF_SS (2*STAGE)                 // states tile 128x17 f32
#define OFF_CS (OFF_SS + 128*17*4)       // C tile 128x17 f32
#define DYN_SMEM (OFF_CS + 128*17*4)     // 82944

__global__ __launch_bounds__(256, 1)
void k_mma(const float* __restrict__ C, float* __restrict__ out) {
    extern __shared__ __align__(1024) char dsm[];
    const int tid  = threadIdx.x;
    const int lane = tid & 31;
    const int wid  = tid >> 5;
    const int wm   = wid & 3;
    const int wn   = wid >> 2;
    const int g    = lane >> 2;
    const int tig  = lane & 3;
    const int rowbase = blockIdx.y * 128;
    const int colbase = blockIdx.x * 128;
    const uint32_t sbase = smem_u32(dsm);
    float* Ss = (float*)(dsm + OFF_SS);
    float* Cs = (float*)(dsm + OFF_CS);

    // ---- issue chunk 0 loads ----
#pragma unroll
    for (int p = 0; p < 4; p++) {
        int idx = p * 256 + tid;
        int r = idx >> 3, c8 = (idx & 7) * 8;
        uint32_t so = swz((uint32_t)(r * 128 + c8 * 2));
        size_t gA = (size_t)(rowbase + r) * HID + c8;
        size_t gB = (size_t)(colbase + r) * HID + c8;
        cp16(sbase + OFF_AH + so, g_xh + gA);
        cp16(sbase + OFF_BH + so, g_Dh + gB);
    }
    cp_commit();

    // ---- load states/C tiles ----
#pragma unroll
    for (int q = 0; q < 2; q++) {
        int idx4 = tid + q * 256;
        int r = idx4 >> 2, kq = (idx4 & 3) * 4;
        float4 s = *(const float4*)&g_states[(size_t)(rowbase + r) * NST + kq];
        float4 c = *(const float4*)&C[(size_t)(colbase + r) * NST + kq];
        Ss[r * 17 + kq + 0] = s.x; Ss[r * 17 + kq + 1] = s.y;
        Ss[r * 17 + kq + 2] = s.z; Ss[r * 17 + kq + 3] = s.w;
        Cs[r * 17 + kq + 0] = c.x; Cs[r * 17 + kq + 1] = c.y;
        Cs[r * 17 + kq + 2] = c.z; Cs[r * 17 + kq + 3] = c.w;
    }
    __syncthreads();

    // ---- init acc = states @ C^T (K=16, fp32 exact) ----
    float acc[2][8][4];
#pragma unroll
    for (int i = 0; i < 2; i++) {
        const int m0 = wm * 32 + i * 16 + g;
        float s0[16], s1[16];
#pragma unroll
        for (int k = 0; k < 16; k++) { s0[k] = Ss[m0 * 17 + k]; s1[k] = Ss[(m0 + 8) * 17 + k]; }
#pragma unroll
        for (int j = 0; j < 8; j++) {
            const int n0 = wn * 64 + j * 8 + tig * 2;
            float c0 = 0.f, c1 = 0.f, c2 = 0.f, c3 = 0.f;
#pragma unroll
            for (int k = 0; k < 16; k++) {
                float e0 = Cs[n0 * 17 + k], e1 = Cs[(n0 + 1) * 17 + k];
                c0 += s0[k] * e0; c1 += s0[k] * e1;
                c2 += s1[k] * e0; c3 += s1[k] * e1;
            }
            acc[i][j][0] = c0; acc[i][j][1] = c1; acc[i][j][2] = c2; acc[i][j][3] = c3;
        }
    }

    // ---- main K loop, 2-stage ----
    for (int c = 0; c < NKC; c++) {
        if (c + 1 < NKC) {
            const uint32_t sb = sbase + ((c + 1) & 1) * STAGE;
            const int kb = (c + 1) * BKC;
#pragma unroll
            for (int p = 0; p < 4; p++) {
                int idx = p * 256 + tid;
                int r = idx >> 3, c8 = (idx & 7) * 8;
                uint32_t so = swz((uint32_t)(r * 128 + c8 * 2));
                size_t gA = (size_t)(rowbase + r) * HID + kb + c8;
                size_t gB = (size_t)(colbase + r) * HID + kb + c8;
                cp16(sb + OFF_AH + so, g_xh + gA);
                cp16(sb + OFF_BH + so, g_Dh + gB);
            }
            cp_commit();
            cp_wait1();
        } else {
            cp_wait0();
        }
        __syncthreads();

        const uint32_t sb = sbase + (c & 1) * STAGE;
#pragma unroll
        for (int ks = 0; ks < BKC / 16; ks++) {
            uint32_t aH[2][4];
#pragma unroll
            for (int i = 0; i < 2; i++) {
                uint32_t off = swz((uint32_t)((wm * 32 + i * 16 + (lane & 15)) * 128 +
                                              (ks * 16 + (lane >> 4) * 8) * 2));
                ldsm4(aH[i], sb + OFF_AH + off);
            }
#pragma unroll
            for (int p = 0; p < 4; p++) {
                uint32_t nloc = wn * 64 + p * 16 + ((lane >> 4) & 1) * 8 + (lane & 7);
                uint32_t kc = ks * 16 + ((lane >> 3) & 1) * 8;
                uint32_t off = swz(nloc * 128 + kc * 2);
                uint32_t rh[4];
                ldsm4(rh, sb + OFF_BH + off);
                mma16816h(acc[0][2*p],   aH[0], rh[0], rh[1]);
                mma16816h(acc[0][2*p+1], aH[0], rh[2], rh[3]);
                mma16816h(acc[1][2*p],   aH[1], rh[0], rh[1]);
                mma16816h(acc[1][2*p+1], aH[1], rh[2], rh[3]);
            }
        }
        __syncthreads();
    }

    // ---- epilogue: pure stores ----
#pragma unroll
    for (int i = 0; i < 2; i++) {
        const int m0 = rowbase + wm * 32 + i * 16 + g;
#pragma unroll
        for (int j = 0; j < 8; j++) {
            const int n0 = colbase + wn * 64 + j * 8 + tig * 2;
            *(float2*)&out[(size_t)m0 * HID + n0]       = make_float2(acc[i][j][0], acc[i][j][1]);
            *(float2*)&out[(size_t)(m0 + 8) * HID + n0] = make_float2(acc[i][j][2], acc[i][j][3]);
        }
    }
}

// ============================================================
// K6: LayerNorm in place
// ============================================================
__global__ __launch_bounds__(256) void k_ln(float* __restrict__ out,
                                            const float* __restrict__ gamma,
                                            const float* __restrict__ beta) {
    __shared__ float rs[8], rs2[8];
    const int row = blockIdx.x;
    const int tid = threadIdx.x;

    float4 v = *(const float4*)&out[(size_t)row * HID + tid * 4];
    float s  = v.x + v.y + v.z + v.w;
    float s2 = v.x*v.x + v.y*v.y + v.z*v.z + v.w*v.w;
#pragma unroll
    for (int o = 16; o > 0; o >>= 1) {
        s  += __shfl_down_sync(0xffffffffu, s,  o);
        s2 += __shfl_down_sync(0xffffffffu, s2, o);
    }
    if ((tid & 31) == 0) { rs[tid >> 5] = s; rs2[tid >> 5] = s2; }
    __syncthreads();
    float ts = 0.f, ts2 = 0.f;
#pragma unroll
    for (int i = 0; i < 8; i++) { ts += rs[i]; ts2 += rs2[i]; }

    const float mu  = ts * (1.f / HID);
    const float var = ts2 * (1.f / HID) - mu * mu;
    const float inv = rsqrtf(var + LN_EPS);

    float4 gm = *(const float4*)&gamma[tid * 4];
    float4 bt = *(const float4*)&beta[tid * 4];
    v.x = (v.x - mu) * inv * gm.x + bt.x;
    v.y = (v.y - mu) * inv * gm.y + bt.y;
    v.z = (v.z - mu) * inv * gm.z + bt.z;
    v.w = (v.w - mu) * inv * gm.w + bt.w;
    *(float4*)&out[(size_t)row * HID + tid * 4] = v;
}

// ============================================================
extern "C" void kernel_launch(void* const* d_in, const int* in_sizes, int n_in,
                              void* d_out, int out_size) {
    const float* x     = (const float*)d_in[0];
    const float* A     = (const float*)d_in[1];
    const float* B     = (const float*)d_in[2];
    const float* C     = (const float*)d_in[3];
    const float* D     = (const float*)d_in[4];
    const float* gamma = (const float*)d_in[5];
    const float* beta  = (const float*)d_in[6];
    float* out = (float*)d_out;
    (void)in_sizes; (void)n_in; (void)out_size;

    cudaFuncSetAttribute(k_mma, cudaFuncAttributeMaxDynamicSharedMemorySize, DYN_SMEM);
    cudaFuncSetAttribute(k_scanpow, cudaFuncAttributeMaxDynamicSharedMemorySize, POW_SMEM);

    __half *xh_p, *dh_p;
    cudaGetSymbolAddress((void**)&xh_p, g_xh);
    cudaGetSymbolAddress((void**)&dh_p, g_Dh);

    const int n4x = NROWS * HID / 4;
    const int n4d = HID * HID / 4;

    // launch 0
    k_cvt_all <<<(n4x + n4d + 255) / 256, 256>>>(x, D, xh_p, dh_p, n4x, n4d);
    // launch 1
    k_xB      <<<NROWS / 128, 256>>>(x, B);
    // launch 2 (32 scan blocks + 1 powers block)
    k_scanpow <<<NCHT / 16 + 1, 256, POW_SMEM>>>(A);
    // launch 3
    k_carry2  <<<NCHT, 256>>>();
    // launch 4
    k_fixup   <<<NROWS / 8, 128>>>();
    // launch 5  (ncu -s 5 -c 1 captures this)
    dim3 g3(HID / 128, NROWS / 128);
    k_mma     <<<g3, 256, DYN_SMEM>>>(C, out);
    // launch 6
    k_ln      <<<NROWS, 256>>>(out, gamma, beta);
}

// round 13
// speedup vs baseline: 1.1659x; 1.0863x over previous
#include <cuda_runtime.h>
#include <cuda_fp16.h>
#include <cstdint>

#define BATCH 4
#define SEQ   4096
#define HID   1024
#define NST   16
#define NROWS (BATCH*SEQ)       // 16384
#define CHUNK 64
#define NCH   (SEQ/CHUNK)       // 64
#define NCHT  (BATCH*NCH)       // 256
#define LN_EPS 1e-5f

// ---- scratch (static device globals) ----
__device__ float g_xB[NROWS*NST];
__device__ float g_states[NROWS*NST];
__device__ float g_finals[NCHT*NST];
__device__ float g_carry[NCHT*NST];
__device__ float g_Apow[(CHUNK+1)*NST*NST];       // A^0..A^64
__device__ float g_Qpow[NCH*NST*NST];             // (A^64)^0..^63
__device__ __half g_xh[(size_t)NROWS*HID];
__device__ __half g_Dh[(size_t)HID*HID];

// ================= PTX helpers ====
__device__ __forceinline__ uint32_t smem_u32(const void* p) {
    uint32_t a;
    asm("{ .reg .u64 t; cvta.to.shared.u64 t, %1; cvt.u32.u64 %0, t; }" : "=r"(a) : "l"(p));
    return a;
}
__device__ __forceinline__ void cp16(uint32_t dst, const void* src) {
    asm volatile("cp.async.cg.shared.global [%0], [%1], 16;" :: "r"(dst), "l"(src) : "memory");
}
__device__ __forceinline__ void cp_commit() {
    asm volatile("cp.async.commit_group;" ::: "memory");
}
__device__ __forceinline__ void cp_wait1() {
    asm volatile("cp.async.wait_group 1;" ::: "memory");
}
__device__ __forceinline__ void cp_wait0() {
    asm volatile("cp.async.wait_group 0;" ::: "memory");
}
__device__ __forceinline__ void ldsm4(uint32_t* r, uint32_t a) {
    asm volatile("ldmatrix.sync.aligned.m8n8.x4.shared.b16 {%0,%1,%2,%3}, [%4];"
                 : "=r"(r[0]), "=r"(r[1]), "=r"(r[2]), "=r"(r[3]) : "r"(a));
}
__device__ __forceinline__ void mma16816h(float* c, const uint32_t* a, uint32_t b0, uint32_t b1) {
    asm volatile(
        "mma.sync.aligned.m16n8k16.row.col.f32.f16.f16.f32 "
        "{%0,%1,%2,%3}, {%4,%5,%6,%7}, {%8,%9}, {%0,%1,%2,%3};"
        : "+f"(c[0]), "+f"(c[1]), "+f"(c[2]), "+f"(c[3])
        : "r"(a[0]), "r"(a[1]), "r"(a[2]), "r"(a[3]), "r"(b0), "r"(b1));
}
static __device__ __forceinline__ uint32_t swz(uint32_t x) { return x ^ ((x >> 3) & 0x70); }

// ============================================================
// K0: conversions: x -> fp16, D -> fp16
// ============================================================
__global__ __launch_bounds__(256) void k_cvt_all(const float* __restrict__ x,
                                                 const float* __restrict__ D,
                                                 __half* __restrict__ xh,
                                                 __half* __restrict__ Dh,
                                                 int n4x, int n4d) {
    int i = blockIdx.x * 256 + threadIdx.x;
    if (i < n4x) {
        float4 v = ((const float4*)x)[i];
        __half2 p0 = __halves2half2(__float2half_rn(v.x), __float2half_rn(v.y));
        __half2 p1 = __halves2half2(__float2half_rn(v.z), __float2half_rn(v.w));
        ((uint2*)xh)[i] = make_uint2(*(uint32_t*)&p0, *(uint32_t*)&p1);
    } else if (i < n4x + n4d) {
        int j = i - n4x;
        float4 v = ((const float4*)D)[j];
        __half2 p0 = __halves2half2(__float2half_rn(v.x), __float2half_rn(v.y));
        __half2 p1 = __halves2half2(__float2half_rn(v.z), __float2half_rn(v.w));
        ((uint2*)Dh)[j] = make_uint2(*(uint32_t*)&p0, *(uint32_t*)&p1);
    }
}

// ============================================================
// K1: xB[row,n] = sum_h xh[row,h] * B[n,h]  (reads fp16 x: half traffic)
// ============================================================
__global__ __launch_bounds__(256) void k_xB(const __half* __restrict__ xh,
                                            const float* __restrict__ B) {
    __shared__ float xs[128][33];
    __shared__ float Bs[NST][33];
    const int tid = threadIdx.x;
    const int rowbase = blockIdx.x * 128;
    const int n  = tid & 15;
    const int rg = tid >> 4;

    float acc[8];
#pragma unroll
    for (int i = 0; i < 8; i++) acc[i] = 0.f;

    for (int kb = 0; kb < HID; kb += 32) {
        // load 128 rows x 32 cols of fp16 = 512 uint4 (8 halves each)
#pragma unroll
        for (int p = 0; p < 2; p++) {
            int idx = tid + p * 256;
            int r  = idx >> 2;
            int kq = (idx & 3) * 8;
            uint4 raw = *(const uint4*)&xh[(size_t)(rowbase + r) * HID + kb + kq];
            __half2 h0 = *(__half2*)&raw.x, h1 = *(__half2*)&raw.y;
            __half2 h2 = *(__half2*)&raw.z, h3 = *(__half2*)&raw.w;
            float2 f0 = __half22float2(h0), f1 = __half22float2(h1);
            float2 f2 = __half22float2(h2), f3 = __half22float2(h3);
            xs[r][kq+0] = f0.x; xs[r][kq+1] = f0.y;
            xs[r][kq+2] = f1.x; xs[r][kq+3] = f1.y;
            xs[r][kq+4] = f2.x; xs[r][kq+5] = f2.y;
            xs[r][kq+6] = f3.x; xs[r][kq+7] = f3.y;
        }
        if (tid < 128) {
            int bn = tid >> 3;
            int kq = (tid & 7) * 4;
            float4 v = *(const float4*)&B[bn * HID + kb + kq];
            Bs[bn][kq+0] = v.x; Bs[bn][kq+1] = v.y; Bs[bn][kq+2] = v.z; Bs[bn][kq+3] = v.w;
        }
        __syncthreads();
#pragma unroll
        for (int k = 0; k < 32; k++) {
            float bv = Bs[n][k];
#pragma unroll
            for (int r = 0; r < 8; r++) acc[r] += xs[rg*8 + r][k] * bv;
        }
        __syncthreads();
    }
#pragma unroll
    for (int r = 0; r < 8; r++)
        g_xB[(rowbase + rg*8 + r) * NST + n] = acc[r];
}

// ============================================================
// K2: combined scan (CHUNK=64; e/o split + u prefetch) + powers
// ============================================================
__global__ __launch_bounds__(256) void k_scanpow(const float* __restrict__ A) {
    __shared__ float sP[33][256];
    const int tid = threadIdx.x;

    if (blockIdx.x < NCHT / 16) {
        const int lane16 = tid & 15;
        const int cid = blockIdx.x * 16 + (tid >> 4);   // 0..255
        const int b = cid >> 6;
        const int c = cid & (NCH - 1);
        const int gb = tid & 16;

        float Arow[NST];
#pragma unroll
        for (int k = 0; k < NST; k++) Arow[k] = A[lane16 * NST + k];

        float s = 0.f;
        const int base = (b * SEQ + c * CHUNK) * NST;
        float u = g_xB[base + lane16];
        for (int i = 0; i < CHUNK; i++) {
            float unext = (i + 1 < CHUNK) ? g_xB[base + (i + 1) * NST + lane16] : 0.f;
            float e = 0.f, o = 0.f;
#pragma unroll
            for (int k = 0; k < NST; k += 2) {
                e += Arow[k]     * __shfl_sync(0xffffffffu, s, gb | k, 32);
                o += Arow[k + 1] * __shfl_sync(0xffffffffu, s, gb | (k + 1), 32);
            }
            s = u + e + o;
            g_states[base + i * NST + lane16] = s;
            u = unext;
        }
        g_finals[cid * NST + lane16] = s;
        return;
    }

    // ---- powers branch (single block): A^0..A^64, Q^0..Q^63 ----
    const int t = tid;
    const int n = t >> 4, m = t & 15;
    const float id = (n == m) ? 1.f : 0.f;
    g_Apow[t] = id;
    g_Apow[256 + t] = A[t];
    sP[1][t] = A[t];
    __syncthreads();
#pragma unroll
    for (int lvl = 1; lvl <= 32; lvl <<= 1) {
        float rowL[16];
#pragma unroll
        for (int k = 0; k < 16; k++) rowL[k] = sP[lvl][n * 16 + k];
        const int qmax = (lvl <= 64 - lvl) ? lvl : 64 - lvl;
        for (int q = 1; q <= qmax; q++) {
            float v = 0.f;
#pragma unroll
            for (int k = 0; k < 16; k++) v += rowL[k] * sP[q][k * 16 + m];
            g_Apow[(lvl + q) * 256 + t] = v;
            if (lvl + q <= 32) sP[lvl + q][t] = v;
        }
        __syncthreads();
    }
    float a64 = g_Apow[64 * 256 + t];
    g_Qpow[t] = id;
    g_Qpow[256 + t] = a64;
    __syncthreads();
    sP[1][t] = a64;
    __syncthreads();
#pragma unroll
    for (int lvl = 1; lvl <= 32; lvl <<= 1) {
        float rowL[16];
#pragma unroll
        for (int k = 0; k < 16; k++) rowL[k] = sP[lvl][n * 16 + k];
        const int qmax = (lvl <= 63 - lvl) ? lvl : 63 - lvl;
        for (int q = 1; q <= qmax; q++) {
            float v = 0.f;
#pragma unroll
            for (int k = 0; k < 16; k++) v += rowL[k] * sP[q][k * 16 + m];
            g_Qpow[(lvl + q) * 256 + t] = v;
            if (lvl + q <= 32) sP[lvl + q][t] = v;
        }
        __syncthreads();
    }
}

// ============================================================
// K3: carry[b,c] = sum_{j<c} Q_{c-1-j} @ finals[b,j]
// ============================================================
__global__ __launch_bounds__(256) void k_carry2() {
    __shared__ float part[16][17];
    const int gid = blockIdx.x;            // 0..255
    const int b = gid >> 6;
    const int c = gid & (NCH - 1);
    const int n  = threadIdx.x & 15;
    const int jg = threadIdx.x >> 4;       // 0..15

    float acc = 0.f;
    for (int j = jg; j < c; j += 16) {
        const float* Qr = &g_Qpow[(c - 1 - j) * 256 + n * NST];
        const float* f  = &g_finals[(b * NCH + j) * NST];
#pragma unroll
        for (int k = 0; k < NST; k++) acc += Qr[k] * f[k];
    }
    part[jg][n] = acc;
    __syncthreads();
    if (threadIdx.x < 16) {
        float s = 0.f;
#pragma unroll
        for (int k = 0; k < 16; k++) s += part[k][threadIdx.x];
        g_carry[gid * NST + threadIdx.x] = s;
    }
}

// ============================================================
// K4: fix-up: states += A^{i+1} @ carry
// ============================================================
__global__ __launch_bounds__(128) void k_fixup() {
    const int tid = threadIdx.x;
    const int n  = tid & 15;
    const int gb = tid & 16;
    const int row = blockIdx.x * 8 + (tid >> 4);
    const int b  = row >> 12;
    const int tt = row & (SEQ - 1);
    const int c  = tt >> 6;
    const int i  = tt & (CHUNK - 1);

    float cv = g_carry[(b * NCH + c) * NST + n];
    const float* Pr = &g_Apow[(i + 1) * 256 + n * NST];
    float v = 0.f;
#pragma unroll
    for (int k = 0; k < NST; k++)
        v += Pr[k] * __shfl_sync(0xffffffffu, cv, gb | k, 32);
    g_states[row * NST + n] += v;
}

// ============================================================
// K5: mma.sync fp16 single-pass GEMM (champion, untouched):
// out = states @ C^T + x @ D^T
// 128x128 tile, 8 warps (32x64 warp tile), BK=64, 2-stage cp.async
// ============================================================
#define BKC 64
#define NKC (HID/BKC)          // 16
#define OFF_AH 0
#define OFF_BH 16384
#define STAGE  32768
#define OFF_SS (2*STAGE)                 // states tile 128x17 f32
#define OFF_CS (OFF_SS + 128*17*4)       // C tile 128x17 f32
#define DYN_SMEM (OFF_CS + 128*17*4)     // 82944

__global__ __launch_bounds__(256, 1)
void k_mma(const float* __restrict__ C, float* __restrict__ out) {
    extern __shared__ __align__(1024) char dsm[];
    const int tid  = threadIdx.x;
    const int lane = tid & 31;
    const int wid  = tid >> 5;
    const int wm   = wid & 3;
    const int wn   = wid >> 2;
    const int g    = lane >> 2;
    const int tig  = lane & 3;
    const int rowbase = blockIdx.y * 128;
    const int colbase = blockIdx.x * 128;
    const uint32_t sbase = smem_u32(dsm);
    float* Ss = (float*)(dsm + OFF_SS);
    float* Cs = (float*)(dsm + OFF_CS);

    // ---- issue chunk 0 loads ----
#pragma unroll
    for (int p = 0; p < 4; p++) {
        int idx = p * 256 + tid;
        int r = idx >> 3, c8 = (idx & 7) * 8;
        uint32_t so = swz((uint32_t)(r * 128 + c8 * 2));
        size_t gA = (size_t)(rowbase + r) * HID + c8;
        size_t gB = (size_t)(colbase + r) * HID + c8;
        cp16(sbase + OFF_AH + so, g_xh + gA);
        cp16(sbase + OFF_BH + so, g_Dh + gB);
    }
    cp_commit();

    // ---- load states/C tiles ----
#pragma unroll
    for (int q = 0; q < 2; q++) {
        int idx4 = tid + q * 256;
        int r = idx4 >> 2, kq = (idx4 & 3) * 4;
        float4 s = *(const float4*)&g_states[(size_t)(rowbase + r) * NST + kq];
        float4 c = *(const float4*)&C[(size_t)(colbase + r) * NST + kq];
        Ss[r * 17 + kq + 0] = s.x; Ss[r * 17 + kq + 1] = s.y;
        Ss[r * 17 + kq + 2] = s.z; Ss[r * 17 + kq + 3] = s.w;
        Cs[r * 17 + kq + 0] = c.x; Cs[r * 17 + kq + 1] = c.y;
        Cs[r * 17 + kq + 2] = c.z; Cs[r * 17 + kq + 3] = c.w;
    }
    __syncthreads();

    // ---- init acc = states @ C^T (K=16, fp32 exact) ----
    float acc[2][8][4];
#pragma unroll
    for (int i = 0; i < 2; i++) {
        const int m0 = wm * 32 + i * 16 + g;
        float s0[16], s1[16];
#pragma unroll
        for (int k = 0; k < 16; k++) { s0[k] = Ss[m0 * 17 + k]; s1[k] = Ss[(m0 + 8) * 17 + k]; }
#pragma unroll
        for (int j = 0; j < 8; j++) {
            const int n0 = wn * 64 + j * 8 + tig * 2;
            float c0 = 0.f, c1 = 0.f, c2 = 0.f, c3 = 0.f;
#pragma unroll
            for (int k = 0; k < 16; k++) {
                float e0 = Cs[n0 * 17 + k], e1 = Cs[(n0 + 1) * 17 + k];
                c0 += s0[k] * e0; c1 += s0[k] * e1;
                c2 += s1[k] * e0; c3 += s1[k] * e1;
            }
            acc[i][j][0] = c0; acc[i][j][1] = c1; acc[i][j][2] = c2; acc[i][j][3] = c3;
        }
    }

    // ---- main K loop, 2-stage ----
    for (int c = 0; c < NKC; c++) {
        if (c + 1 < NKC) {
            const uint32_t sb = sbase + ((c + 1) & 1) * STAGE;
            const int kb = (c + 1) * BKC;
#pragma unroll
            for (int p = 0; p < 4; p++) {
                int idx = p * 256 + tid;
                int r = idx >> 3, c8 = (idx & 7) * 8;
                uint32_t so = swz((uint32_t)(r * 128 + c8 * 2));
                size_t gA = (size_t)(rowbase + r) * HID + kb + c8;
                size_t gB = (size_t)(colbase + r) * HID + kb + c8;
                cp16(sb + OFF_AH + so, g_xh + gA);
                cp16(sb + OFF_BH + so, g_Dh + gB);
            }
            cp_commit();
            cp_wait1();
        } else {
            cp_wait0();
        }
        __syncthreads();

        const uint32_t sb = sbase + (c & 1) * STAGE;
#pragma unroll
        for (int ks = 0; ks < BKC / 16; ks++) {
            uint32_t aH[2][4];
#pragma unroll
            for (int i = 0; i < 2; i++) {
                uint32_t off = swz((uint32_t)((wm * 32 + i * 16 + (lane & 15)) * 128 +
                                              (ks * 16 + (lane >> 4) * 8) * 2));
                ldsm4(aH[i], sb + OFF_AH + off);
            }
#pragma unroll
            for (int p = 0; p < 4; p++) {
                uint32_t nloc = wn * 64 + p * 16 + ((lane >> 4) & 1) * 8 + (lane & 7);
                uint32_t kc = ks * 16 + ((lane >> 3) & 1) * 8;
                uint32_t off = swz(nloc * 128 + kc * 2);
                uint32_t rh[4];
                ldsm4(rh, sb + OFF_BH + off);
                mma16816h(acc[0][2*p],   aH[0], rh[0], rh[1]);
                mma16816h(acc[0][2*p+1], aH[0], rh[2], rh[3]);
                mma16816h(acc[1][2*p],   aH[1], rh[0], rh[1]);
                mma16816h(acc[1][2*p+1], aH[1], rh[2], rh[3]);
            }
        }
        __syncthreads();
    }

    // ---- epilogue: pure stores ----
#pragma unroll
    for (int i = 0; i < 2; i++) {
        const int m0 = rowbase + wm * 32 + i * 16 + g;
#pragma unroll
        for (int j = 0; j < 8; j++) {
            const int n0 = colbase + wn * 64 + j * 8 + tig * 2;
            *(float2*)&out[(size_t)m0 * HID + n0]       = make_float2(acc[i][j][0], acc[i][j][1]);
            *(float2*)&out[(size_t)(m0 + 8) * HID + n0] = make_float2(acc[i][j][2], acc[i][j][3]);
        }
    }
}

// ============================================================
// K6: LayerNorm in place
// ============================================================
__global__ __launch_bounds__(256) void k_ln(float* __restrict__ out,
                                            const float* __restrict__ gamma,
                                            const float* __restrict__ beta) {
    __shared__ float rs[8], rs2[8];
    const int row = blockIdx.x;
    const int tid = threadIdx.x;

    float4 v = *(const float4*)&out[(size_t)row * HID + tid * 4];
    float s  = v.x + v.y + v.z + v.w;
    float s2 = v.x*v.x + v.y*v.y + v.z*v.z + v.w*v.w;
#pragma unroll
    for (int o = 16; o > 0; o >>= 1) {
        s  += __shfl_down_sync(0xffffffffu, s,  o);
        s2 += __shfl_down_sync(0xffffffffu, s2, o);
    }
    if ((tid & 31) == 0) { rs[tid >> 5] = s; rs2[tid >> 5] = s2; }
    __syncthreads();
    float ts = 0.f, ts2 = 0.f;
#pragma unroll
    for (int i = 0; i < 8; i++) { ts += rs[i]; ts2 += rs2[i]; }

    const float mu  = ts * (1.f / HID);
    const float var = ts2 * (1.f / HID) - mu * mu;
    const float inv = rsqrtf(var + LN_EPS);

    float4 gm = *(const float4*)&gamma[tid * 4];
    float4 bt = *(const float4*)&beta[tid * 4];
    v.x = (v.x - mu) * inv * gm.x + bt.x;
    v.y = (v.y - mu) * inv * gm.y + bt.y;
    v.z = (v.z - mu) * inv * gm.z + bt.z;
    v.w = (v.w - mu) * inv * gm.w + bt.w;
    *(float4*)&out[(size_t)row * HID + tid * 4] = v;
}

// ============================================================
extern "C" void kernel_launch(void* const* d_in, const int* in_sizes, int n_in,
                              void* d_out, int out_size) {
    const float* x     = (const float*)d_in[0];
    const float* A     = (const float*)d_in[1];
    const float* B     = (const float*)d_in[2];
    const float* C     = (const float*)d_in[3];
    const float* D     = (const float*)d_in[4];
    const float* gamma = (const float*)d_in[5];
    const float* beta  = (const float*)d_in[6];
    float* out = (float*)d_out;
    (void)in_sizes; (void)n_in; (void)out_size;

    cudaFuncSetAttribute(k_mma, cudaFuncAttributeMaxDynamicSharedMemorySize, DYN_SMEM);

    __half *xh_p, *dh_p;
    cudaGetSymbolAddress((void**)&xh_p, g_xh);
    cudaGetSymbolAddress((void**)&dh_p, g_Dh);

    const int n4x = NROWS * HID / 4;
    const int n4d = HID * HID / 4;

    // launch 0
    k_cvt_all <<<(n4x + n4d + 255) / 256, 256>>>(x, D, xh_p, dh_p, n4x, n4d);
    // launch 1  (reads fp16 x)
    k_xB      <<<NROWS / 128, 256>>>(xh_p, B);
    // launch 2
    k_scanpow <<<NCHT / 16 + 1, 256>>>(A);
    // launch 3
    k_carry2  <<<NCHT, 256>>>();
    // launch 4
    k_fixup   <<<NROWS / 8, 128>>>();
    // launch 5
    dim3 g3(HID / 128, NROWS / 128);
    k_mma     <<<g3, 256, DYN_SMEM>>>(C, out);
    // launch 6
    k_ln      <<<NROWS, 256>>>(out, gamma, beta);
}

// round 14
// speedup vs baseline: 1.1759x; 1.0086x over previous
#include <cuda_runtime.h>
#include <cuda_fp16.h>
#include <cstdint>

#define BATCH 4
#define SEQ   4096
#define HID   1024
#define NST   16
#define NROWS (BATCH*SEQ)       // 16384
#define CHUNK 64
#define NCH   (SEQ/CHUNK)       // 64
#define NCHT  (BATCH*NCH)       // 256
#define LN_EPS 1e-5f

// ---- scratch (static device globals) ----
__device__ float g_xB[NROWS*NST];
__device__ float g_states[NROWS*NST];
__device__ float g_finals[NCHT*NST];
__device__ float g_carry[NCHT*NST];
__device__ float g_Apow[(CHUNK+1)*NST*NST];       // A^0..A^64
__device__ float g_Qpow[NCH*NST*NST];             // (A^64)^0..^63
__device__ __half g_xh[(size_t)NROWS*HID];
__device__ __half g_Dh[(size_t)HID*HID];

// ================= PTX helpers ====
__device__ __forceinline__ uint32_t smem_u32(const void* p) {
    uint32_t a;
    asm("{ .reg .u64 t; cvta.to.shared.u64 t, %1; cvt.u32.u64 %0, t; }" : "=r"(a) : "l"(p));
    return a;
}
__device__ __forceinline__ void cp16(uint32_t dst, const void* src) {
    asm volatile("cp.async.cg.shared.global [%0], [%1], 16;" :: "r"(dst), "l"(src) : "memory");
}
__device__ __forceinline__ void cp_commit() {
    asm volatile("cp.async.commit_group;" ::: "memory");
}
__device__ __forceinline__ void cp_wait1() {
    asm volatile("cp.async.wait_group 1;" ::: "memory");
}
__device__ __forceinline__ void cp_wait0() {
    asm volatile("cp.async.wait_group 0;" ::: "memory");
}
__device__ __forceinline__ void ldsm4(uint32_t* r, uint32_t a) {
    asm volatile("ldmatrix.sync.aligned.m8n8.x4.shared.b16 {%0,%1,%2,%3}, [%4];"
                 : "=r"(r[0]), "=r"(r[1]), "=r"(r[2]), "=r"(r[3]) : "r"(a));
}
__device__ __forceinline__ void mma16816h(float* c, const uint32_t* a, uint32_t b0, uint32_t b1) {
    asm volatile(
        "mma.sync.aligned.m16n8k16.row.col.f32.f16.f16.f32 "
        "{%0,%1,%2,%3}, {%4,%5,%6,%7}, {%8,%9}, {%0,%1,%2,%3};"
        : "+f"(c[0]), "+f"(c[1]), "+f"(c[2]), "+f"(c[3])
        : "r"(a[0]), "r"(a[1]), "r"(a[2]), "r"(a[3]), "r"(b0), "r"(b1));
}
static __device__ __forceinline__ uint32_t swz(uint32_t x) { return x ^ ((x >> 3) & 0x70); }

// ============================================================
// K0: conversions: x -> fp16, D -> fp16
// ============================================================
__global__ __launch_bounds__(256) void k_cvt_all(const float* __restrict__ x,
                                                 const float* __restrict__ D,
                                                 __half* __restrict__ xh,
                                                 __half* __restrict__ Dh,
                                                 int n4x, int n4d) {
    int i = blockIdx.x * 256 + threadIdx.x;
    if (i < n4x) {
        float4 v = ((const float4*)x)[i];
        __half2 p0 = __halves2half2(__float2half_rn(v.x), __float2half_rn(v.y));
        __half2 p1 = __halves2half2(__float2half_rn(v.z), __float2half_rn(v.w));
        ((uint2*)xh)[i] = make_uint2(*(uint32_t*)&p0, *(uint32_t*)&p1);
    } else if (i < n4x + n4d) {
        int j = i - n4x;
        float4 v = ((const float4*)D)[j];
        __half2 p0 = __halves2half2(__float2half_rn(v.x), __float2half_rn(v.y));
        __half2 p1 = __halves2half2(__float2half_rn(v.z), __float2half_rn(v.w));
        ((uint2*)Dh)[j] = make_uint2(*(uint32_t*)&p0, *(uint32_t*)&p1);
    }
}

// ============================================================
// K1: xB[row,n] = sum_h xh[row,h] * B[n,h]
// 64 rows/block, grid 256 (better SM fill than 128-row/128-block)
// ============================================================
__global__ __launch_bounds__(256) void k_xB(const __half* __restrict__ xh,
                                            const float* __restrict__ B) {
    __shared__ float xs[64][33];
    __shared__ float Bs[NST][33];
    const int tid = threadIdx.x;
    const int rowbase = blockIdx.x * 64;
    const int n  = tid & 15;
    const int rg = tid >> 4;     // 0..15, each handles 4 rows

    float acc[4];
#pragma unroll
    for (int i = 0; i < 4; i++) acc[i] = 0.f;

    for (int kb = 0; kb < HID; kb += 32) {
        // 64 rows x 32 halves = 256 uint4, one per thread
        {
            int r  = tid >> 2;
            int kq = (tid & 3) * 8;
            uint4 raw = *(const uint4*)&xh[(size_t)(rowbase + r) * HID + kb + kq];
            __half2 h0 = *(__half2*)&raw.x, h1 = *(__half2*)&raw.y;
            __half2 h2 = *(__half2*)&raw.z, h3 = *(__half2*)&raw.w;
            float2 f0 = __half22float2(h0), f1 = __half22float2(h1);
            float2 f2 = __half22float2(h2), f3 = __half22float2(h3);
            xs[r][kq+0] = f0.x; xs[r][kq+1] = f0.y;
            xs[r][kq+2] = f1.x; xs[r][kq+3] = f1.y;
            xs[r][kq+4] = f2.x; xs[r][kq+5] = f2.y;
            xs[r][kq+6] = f3.x; xs[r][kq+7] = f3.y;
        }
        if (tid < 128) {
            int bn = tid >> 3;
            int kq = (tid & 7) * 4;
            float4 v = *(const float4*)&B[bn * HID + kb + kq];
            Bs[bn][kq+0] = v.x; Bs[bn][kq+1] = v.y; Bs[bn][kq+2] = v.z; Bs[bn][kq+3] = v.w;
        }
        __syncthreads();
#pragma unroll
        for (int k = 0; k < 32; k++) {
            float bv = Bs[n][k];
#pragma unroll
            for (int r = 0; r < 4; r++) acc[r] += xs[rg*4 + r][k] * bv;
        }
        __syncthreads();
    }
#pragma unroll
    for (int r = 0; r < 4; r++)
        g_xB[(rowbase + rg*4 + r) * NST + n] = acc[r];
}

// ============================================================
// K2: combined scan (CHUNK=64; e/o split + 4-deep prefetch) + powers
// ============================================================
__global__ __launch_bounds__(256) void k_scanpow(const float* __restrict__ A) {
    __shared__ float sP[33][256];
    const int tid = threadIdx.x;

    if (blockIdx.x < NCHT / 16) {
        const int lane16 = tid & 15;
        const int cid = blockIdx.x * 16 + (tid >> 4);   // 0..255
        const int b = cid >> 6;
        const int c = cid & (NCH - 1);
        const int gb = tid & 16;

        float Arow[NST];
#pragma unroll
        for (int k = 0; k < NST; k++) Arow[k] = A[lane16 * NST + k];

        float s = 0.f;
        const int base = (b * SEQ + c * CHUNK) * NST;
        float ub[4];
#pragma unroll
        for (int q = 0; q < 4; q++) ub[q] = g_xB[base + q * NST + lane16];

        for (int i = 0; i < CHUNK; i++) {
            float u = ub[i & 3];
            if (i + 4 < CHUNK) ub[i & 3] = g_xB[base + (i + 4) * NST + lane16];
            float e = 0.f, o = 0.f;
#pragma unroll
            for (int k = 0; k < NST; k += 2) {
                e += Arow[k]     * __shfl_sync(0xffffffffu, s, gb | k, 32);
                o += Arow[k + 1] * __shfl_sync(0xffffffffu, s, gb | (k + 1), 32);
            }
            s = u + e + o;
            g_states[base + i * NST + lane16] = s;
        }
        g_finals[cid * NST + lane16] = s;
        return;
    }

    // ---- powers branch (single block): A^0..A^64, Q^0..Q^63 ----
    const int t = tid;
    const int n = t >> 4, m = t & 15;
    const float id = (n == m) ? 1.f : 0.f;
    g_Apow[t] = id;
    g_Apow[256 + t] = A[t];
    sP[1][t] = A[t];
    __syncthreads();
#pragma unroll
    for (int lvl = 1; lvl <= 32; lvl <<= 1) {
        float rowL[16];
#pragma unroll
        for (int k = 0; k < 16; k++) rowL[k] = sP[lvl][n * 16 + k];
        const int qmax = (lvl <= 64 - lvl) ? lvl : 64 - lvl;
        for (int q = 1; q <= qmax; q++) {
            float v = 0.f;
#pragma unroll
            for (int k = 0; k < 16; k++) v += rowL[k] * sP[q][k * 16 + m];
            g_Apow[(lvl + q) * 256 + t] = v;
            if (lvl + q <= 32) sP[lvl + q][t] = v;
        }
        __syncthreads();
    }
    float a64 = g_Apow[64 * 256 + t];
    g_Qpow[t] = id;
    g_Qpow[256 + t] = a64;
    __syncthreads();
    sP[1][t] = a64;
    __syncthreads();
#pragma unroll
    for (int lvl = 1; lvl <= 32; lvl <<= 1) {
        float rowL[16];
#pragma unroll
        for (int k = 0; k < 16; k++) rowL[k] = sP[lvl][n * 16 + k];
        const int qmax = (lvl <= 63 - lvl) ? lvl : 63 - lvl;
        for (int q = 1; q <= qmax; q++) {
            float v = 0.f;
#pragma unroll
            for (int k = 0; k < 16; k++) v += rowL[k] * sP[q][k * 16 + m];
            g_Qpow[(lvl + q) * 256 + t] = v;
            if (lvl + q <= 32) sP[lvl + q][t] = v;
        }
        __syncthreads();
    }
}

// ============================================================
// K3: carry[b,c] = sum_{j<c} Q_{c-1-j} @ finals[b,j]
// ============================================================
__global__ __launch_bounds__(256) void k_carry2() {
    __shared__ float part[16][17];
    const int gid = blockIdx.x;            // 0..255
    const int b = gid >> 6;
    const int c = gid & (NCH - 1);
    const int n  = threadIdx.x & 15;
    const int jg = threadIdx.x >> 4;       // 0..15

    float acc = 0.f;
    for (int j = jg; j < c; j += 16) {
        const float* Qr = &g_Qpow[(c - 1 - j) * 256 + n * NST];
        const float* f  = &g_finals[(b * NCH + j) * NST];
#pragma unroll
        for (int k = 0; k < NST; k++) acc += Qr[k] * f[k];
    }
    part[jg][n] = acc;
    __syncthreads();
    if (threadIdx.x < 16) {
        float s = 0.f;
#pragma unroll
        for (int k = 0; k < 16; k++) s += part[k][threadIdx.x];
        g_carry[gid * NST + threadIdx.x] = s;
    }
}

// ============================================================
// K4: fix-up: states += A^{i+1} @ carry
// ============================================================
__global__ __launch_bounds__(128) void k_fixup() {
    const int tid = threadIdx.x;
    const int n  = tid & 15;
    const int gb = tid & 16;
    const int row = blockIdx.x * 8 + (tid >> 4);
    const int b  = row >> 12;
    const int tt = row & (SEQ - 1);
    const int c  = tt >> 6;
    const int i  = tt & (CHUNK - 1);

    float cv = g_carry[(b * NCH + c) * NST + n];
    const float* Pr = &g_Apow[(i + 1) * 256 + n * NST];
    float v = 0.f;
#pragma unroll
    for (int k = 0; k < NST; k++)
        v += Pr[k] * __shfl_sync(0xffffffffu, cv, gb | k, 32);
    g_states[row * NST + n] += v;
}

// ============================================================
// K5: mma.sync fp16 single-pass GEMM (champion, untouched):
// out = states @ C^T + x @ D^T
// 128x128 tile, 8 warps (32x64 warp tile), BK=64, 2-stage cp.async
// ============================================================
#define BKC 64
#define NKC (HID/BKC)          // 16
#define OFF_AH 0
#define OFF_BH 16384
#define STAGE  32768
#define OFF_SS (2*STAGE)                 // states tile 128x17 f32
#define OFF_CS (OFF_SS + 128*17*4)       // C tile 128x17 f32
#define DYN_SMEM (OFF_CS + 128*17*4)     // 82944

__global__ __launch_bounds__(256, 1)
void k_mma(const float* __restrict__ C, float* __restrict__ out) {
    extern __shared__ __align__(1024) char dsm[];
    const int tid  = threadIdx.x;
    const int lane = tid & 31;
    const int wid  = tid >> 5;
    const int wm   = wid & 3;
    const int wn   = wid >> 2;
    const int g    = lane >> 2;
    const int tig  = lane & 3;
    const int rowbase = blockIdx.y * 128;
    const int colbase = blockIdx.x * 128;
    const uint32_t sbase = smem_u32(dsm);
    float* Ss = (float*)(dsm + OFF_SS);
    float* Cs = (float*)(dsm + OFF_CS);

    // ---- issue chunk 0 loads ----
#pragma unroll
    for (int p = 0; p < 4; p++) {
        int idx = p * 256 + tid;
        int r = idx >> 3, c8 = (idx & 7) * 8;
        uint32_t so = swz((uint32_t)(r * 128 + c8 * 2));
        size_t gA = (size_t)(rowbase + r) * HID + c8;
        size_t gB = (size_t)(colbase + r) * HID + c8;
        cp16(sbase + OFF_AH + so, g_xh + gA);
        cp16(sbase + OFF_BH + so, g_Dh + gB);
    }
    cp_commit();

    // ---- load states/C tiles ----
#pragma unroll
    for (int q = 0; q < 2; q++) {
        int idx4 = tid + q * 256;
        int r = idx4 >> 2, kq = (idx4 & 3) * 4;
        float4 s = *(const float4*)&g_states[(size_t)(rowbase + r) * NST + kq];
        float4 c = *(const float4*)&C[(size_t)(colbase + r) * NST + kq];
        Ss[r * 17 + kq + 0] = s.x; Ss[r * 17 + kq + 1] = s.y;
        Ss[r * 17 + kq + 2] = s.z; Ss[r * 17 + kq + 3] = s.w;
        Cs[r * 17 + kq + 0] = c.x; Cs[r * 17 + kq + 1] = c.y;
        Cs[r * 17 + kq + 2] = c.z; Cs[r * 17 + kq + 3] = c.w;
    }
    __syncthreads();

    // ---- init acc = states @ C^T (K=16, fp32 exact) ----
    float acc[2][8][4];
#pragma unroll
    for (int i = 0; i < 2; i++) {
        const int m0 = wm * 32 + i * 16 + g;
        float s0[16], s1[16];
#pragma unroll
        for (int k = 0; k < 16; k++) { s0[k] = Ss[m0 * 17 + k]; s1[k] = Ss[(m0 + 8) * 17 + k]; }
#pragma unroll
        for (int j = 0; j < 8; j++) {
            const int n0 = wn * 64 + j * 8 + tig * 2;
            float c0 = 0.f, c1 = 0.f, c2 = 0.f, c3 = 0.f;
#pragma unroll
            for (int k = 0; k < 16; k++) {
                float e0 = Cs[n0 * 17 + k], e1 = Cs[(n0 + 1) * 17 + k];
                c0 += s0[k] * e0; c1 += s0[k] * e1;
                c2 += s1[k] * e0; c3 += s1[k] * e1;
            }
            acc[i][j][0] = c0; acc[i][j][1] = c1; acc[i][j][2] = c2; acc[i][j][3] = c3;
        }
    }

    // ---- main K loop, 2-stage ----
    for (int c = 0; c < NKC; c++) {
        if (c + 1 < NKC) {
            const uint32_t sb = sbase + ((c + 1) & 1) * STAGE;
            const int kb = (c + 1) * BKC;
#pragma unroll
            for (int p = 0; p < 4; p++) {
                int idx = p * 256 + tid;
                int r = idx >> 3, c8 = (idx & 7) * 8;
                uint32_t so = swz((uint32_t)(r * 128 + c8 * 2));
                size_t gA = (size_t)(rowbase + r) * HID + kb + c8;
                size_t gB = (size_t)(colbase + r) * HID + kb + c8;
                cp16(sb + OFF_AH + so, g_xh + gA);
                cp16(sb + OFF_BH + so, g_Dh + gB);
            }
            cp_commit();
            cp_wait1();
        } else {
            cp_wait0();
        }
        __syncthreads();

        const uint32_t sb = sbase + (c & 1) * STAGE;
#pragma unroll
        for (int ks = 0; ks < BKC / 16; ks++) {
            uint32_t aH[2][4];
#pragma unroll
            for (int i = 0; i < 2; i++) {
                uint32_t off = swz((uint32_t)((wm * 32 + i * 16 + (lane & 15)) * 128 +
                                              (ks * 16 + (lane >> 4) * 8) * 2));
                ldsm4(aH[i], sb + OFF_AH + off);
            }
#pragma unroll
            for (int p = 0; p < 4; p++) {
                uint32_t nloc = wn * 64 + p * 16 + ((lane >> 4) & 1) * 8 + (lane & 7);
                uint32_t kc = ks * 16 + ((lane >> 3) & 1) * 8;
                uint32_t off = swz(nloc * 128 + kc * 2);
                uint32_t rh[4];
                ldsm4(rh, sb + OFF_BH + off);
                mma16816h(acc[0][2*p],   aH[0], rh[0], rh[1]);
                mma16816h(acc[0][2*p+1], aH[0], rh[2], rh[3]);
                mma16816h(acc[1][2*p],   aH[1], rh[0], rh[1]);
                mma16816h(acc[1][2*p+1], aH[1], rh[2], rh[3]);
            }
        }
        __syncthreads();
    }

    // ---- epilogue: pure stores ----
#pragma unroll
    for (int i = 0; i < 2; i++) {
        const int m0 = rowbase + wm * 32 + i * 16 + g;
#pragma unroll
        for (int j = 0; j < 8; j++) {
            const int n0 = colbase + wn * 64 + j * 8 + tig * 2;
            *(float2*)&out[(size_t)m0 * HID + n0]       = make_float2(acc[i][j][0], acc[i][j][1]);
            *(float2*)&out[(size_t)(m0 + 8) * HID + n0] = make_float2(acc[i][j][2], acc[i][j][3]);
        }
    }
}

// ============================================================
// K6: LayerNorm in place
// ============================================================
__global__ __launch_bounds__(256) void k_ln(float* __restrict__ out,
                                            const float* __restrict__ gamma,
                                            const float* __restrict__ beta) {
    __shared__ float rs[8], rs2[8];
    const int row = blockIdx.x;
    const int tid = threadIdx.x;

    float4 v = *(const float4*)&out[(size_t)row * HID + tid * 4];
    float s  = v.x + v.y + v.z + v.w;
    float s2 = v.x*v.x + v.y*v.y + v.z*v.z + v.w*v.w;
#pragma unroll
    for (int o = 16; o > 0; o >>= 1) {
        s  += __shfl_down_sync(0xffffffffu, s,  o);
        s2 += __shfl_down_sync(0xffffffffu, s2, o);
    }
    if ((tid & 31) == 0) { rs[tid >> 5] = s; rs2[tid >> 5] = s2; }
    __syncthreads();
    float ts = 0.f, ts2 = 0.f;
#pragma unroll
    for (int i = 0; i < 8; i++) { ts += rs[i]; ts2 += rs2[i]; }

    const float mu  = ts * (1.f / HID);
    const float var = ts2 * (1.f / HID) - mu * mu;
    const float inv = rsqrtf(var + LN_EPS);

    float4 gm = *(const float4*)&gamma[tid * 4];
    float4 bt = *(const float4*)&beta[tid * 4];
    v.x = (v.x - mu) * inv * gm.x + bt.x;
    v.y = (v.y - mu) * inv * gm.y + bt.y;
    v.z = (v.z - mu) * inv * gm.z + bt.z;
    v.w = (v.w - mu) * inv * gm.w + bt.w;
    *(float4*)&out[(size_t)row * HID + tid * 4] = v;
}

// ============================================================
extern "C" void kernel_launch(void* const* d_in, const int* in_sizes, int n_in,
                              void* d_out, int out_size) {
    const float* x     = (const float*)d_in[0];
    const float* A     = (const float*)d_in[1];
    const float* B     = (const float*)d_in[2];
    const float* C     = (const float*)d_in[3];
    const float* D     = (const float*)d_in[4];
    const float* gamma = (const float*)d_in[5];
    const float* beta  = (const float*)d_in[6];
    float* out = (float*)d_out;
    (void)in_sizes; (void)n_in; (void)out_size;

    cudaFuncSetAttribute(k_mma, cudaFuncAttributeMaxDynamicSharedMemorySize, DYN_SMEM);

    __half *xh_p, *dh_p;
    cudaGetSymbolAddress((void**)&xh_p, g_xh);
    cudaGetSymbolAddress((void**)&dh_p, g_Dh);

    const int n4x = NROWS * HID / 4;
    const int n4d = HID * HID / 4;

    // launch 0
    k_cvt_all <<<(n4x + n4d + 255) / 256, 256>>>(x, D, xh_p, dh_p, n4x, n4d);
    // launch 1  (reads fp16 x; 64 rows/block, grid 256)
    k_xB      <<<NROWS / 64, 256>>>(xh_p, B);
    // launch 2
    k_scanpow <<<NCHT / 16 + 1, 256>>>(A);
    // launch 3
    k_carry2  <<<NCHT, 256>>>();
    // launch 4
    k_fixup   <<<NROWS / 8, 128>>>();
    // launch 5
    dim3 g3(HID / 128, NROWS / 128);
    k_mma     <<<g3, 256, DYN_SMEM>>>(C, out);
    // launch 6
    k_ln      <<<NROWS, 256>>>(out, gamma, beta);
}